// round 2
// baseline (speedup 1.0000x reference)
#include <cuda_runtime.h>

#define VOCAB 32000
#define EMB   256
#define UNITS 1024
#define BATCH 64
#define TLEN  512
#define N3    3072

#define GRID  128
#define TPB   256
#define CPC   8            // column-pairs per CTA
#define KCH   128          // k-chunk (staged in smem)
#define NCHUNK (UNITS / KCH)

// -------------------- device globals (no allocation allowed) ---------------
__device__ float g_xproj[(size_t)BATCH * TLEN * N3];   // [B*T, 3U]
__device__ float g_h[BATCH * UNITS];                   // current hidden
__device__ float g_rh[BATCH * UNITS];                  // r * h
__device__ unsigned g_count = 0;
__device__ unsigned g_gen   = 0;

// -------------------- grid barrier (all GRID CTAs co-resident) -------------
__device__ __forceinline__ void grid_barrier()
{
    __syncthreads();
    if (threadIdx.x == 0) {
        __threadfence();
        volatile unsigned* vgen = &g_gen;
        unsigned target = *vgen + 1u;
        unsigned old = atomicAdd(&g_count, 1u);
        if (old == GRID - 1u) {
            *((volatile unsigned*)&g_count) = 0u;
            __threadfence();
            *vgen = target;
        } else {
            while (*vgen != target) __nanosleep(64);
        }
    }
    __syncthreads();
}

// ---------------------------------------------------------------------------
// Kernel 1: xproj = gather(emb_table, x) @ kernel + bias   (unchanged, known OK)
// C[32768, 3072], K=256. CTA tile 128x128, 256 threads, 8x8 per thread.
// ---------------------------------------------------------------------------
__global__ __launch_bounds__(256) void xproj_kernel(
    const int* __restrict__ x,
    const float* __restrict__ emb_table,
    const float* __restrict__ kernelW,
    const float* __restrict__ bias)
{
    __shared__ __align__(16) float As[16][128];
    __shared__ __align__(16) float Bs[16][128];

    const int tid = threadIdx.x;
    const int m0 = blockIdx.y * 128;
    const int n0 = blockIdx.x * 128;

    const int arow = tid & 127;
    const int kq0  = tid >> 7;
    const int token = x[m0 + arow];
    const float* aptr = emb_table + (size_t)token * EMB;

    const int bk = tid >> 4;
    const int bq = tid & 15;
    const int ty = tid >> 4;
    const int tx = tid & 15;

    float acc[8][8];
#pragma unroll
    for (int i = 0; i < 8; i++)
#pragma unroll
        for (int j = 0; j < 8; j++) acc[i][j] = 0.f;

    for (int k0 = 0; k0 < EMB; k0 += 16) {
        float4 va0 = *(const float4*)(aptr + k0 + kq0 * 4);
        float4 va1 = *(const float4*)(aptr + k0 + (kq0 + 2) * 4);
        const float* wrow = kernelW + (size_t)(k0 + bk) * N3 + n0;
        float4 vb0 = *(const float4*)(wrow + bq * 4);
        float4 vb1 = *(const float4*)(wrow + bq * 4 + 64);

        __syncthreads();
        As[kq0 * 4 + 0][arow] = va0.x;
        As[kq0 * 4 + 1][arow] = va0.y;
        As[kq0 * 4 + 2][arow] = va0.z;
        As[kq0 * 4 + 3][arow] = va0.w;
        As[(kq0 + 2) * 4 + 0][arow] = va1.x;
        As[(kq0 + 2) * 4 + 1][arow] = va1.y;
        As[(kq0 + 2) * 4 + 2][arow] = va1.z;
        As[(kq0 + 2) * 4 + 3][arow] = va1.w;
        Bs[bk][bq * 4 + 0] = vb0.x;
        Bs[bk][bq * 4 + 1] = vb0.y;
        Bs[bk][bq * 4 + 2] = vb0.z;
        Bs[bk][bq * 4 + 3] = vb0.w;
        Bs[bk][bq * 4 + 64] = vb1.x;
        Bs[bk][bq * 4 + 65] = vb1.y;
        Bs[bk][bq * 4 + 66] = vb1.z;
        Bs[bk][bq * 4 + 67] = vb1.w;
        __syncthreads();

#pragma unroll
        for (int k = 0; k < 16; k++) {
            float4 a0 = *(const float4*)(&As[k][ty * 8]);
            float4 a1 = *(const float4*)(&As[k][ty * 8 + 4]);
            float4 b0 = *(const float4*)(&Bs[k][tx * 8]);
            float4 b1 = *(const float4*)(&Bs[k][tx * 8 + 4]);
            float av[8] = {a0.x, a0.y, a0.z, a0.w, a1.x, a1.y, a1.z, a1.w};
            float bv[8] = {b0.x, b0.y, b0.z, b0.w, b1.x, b1.y, b1.z, b1.w};
#pragma unroll
            for (int i = 0; i < 8; i++)
#pragma unroll
                for (int j = 0; j < 8; j++)
                    acc[i][j] = fmaf(av[i], bv[j], acc[i][j]);
        }
    }

#pragma unroll
    for (int i = 0; i < 8; i++) {
        const int row = m0 + ty * 8 + i;
        float* dst = &g_xproj[(size_t)row * N3 + n0 + tx * 8];
        const float* bptr = bias + n0 + tx * 8;
        float4 o0, o1;
        o0.x = acc[i][0] + bptr[0];
        o0.y = acc[i][1] + bptr[1];
        o0.z = acc[i][2] + bptr[2];
        o0.w = acc[i][3] + bptr[3];
        o1.x = acc[i][4] + bptr[4];
        o1.y = acc[i][5] + bptr[5];
        o1.z = acc[i][6] + bptr[6];
        o1.w = acc[i][7] + bptr[7];
        *(float4*)dst = o0;
        *(float4*)(dst + 4) = o1;
    }
}

// ---------------------------------------------------------------------------
// Kernel 2: persistent GRU scan. 128 CTAs x 256 threads, weights in SMEM.
// CTA c owns columns [c*8, c*8+8) of each gate (z, r, h).
// SMEM layout (floats):
//   wzs[8][1028]  @ 0          (pad +4 vs 1024: bank-conflict-free)
//   wrs[8][1028]  @ 8224
//   whs[8][1028]  @ 16448
//   hs  [2][64][132] @ 24672   (staged h / rh k-chunks, pad +4)
//   zs  [64][8]   @ 41568
// total 42080 floats = 168320 bytes (dynamic, opt-in)
// ---------------------------------------------------------------------------
#define SM_WZ 0
#define SM_WR 8224
#define SM_WH 16448
#define SM_HS 24672
#define SM_HSB 8448       // one staging buffer = 64*132
#define SM_ZS 41568
#define SMEM_FLOATS 42080

__global__ void __launch_bounds__(TPB, 1) gru_scan(
    const float* __restrict__ hidden,
    const float* __restrict__ rk,
    float* __restrict__ out)
{
    extern __shared__ float sm[];
    float* wzs = sm + SM_WZ;
    float* wrs = sm + SM_WR;
    float* whs = sm + SM_WH;
    float* zs  = sm + SM_ZS;

    const int tid = threadIdx.x;
    const int cta = blockIdx.x;
    const int cc  = tid & 7;          // local column 0..7
    const int bb  = tid >> 3;         // 0..31
    const int b0  = bb * 2;
    const int b1  = bb * 2 + 1;
    const int col = cta * CPC + cc;   // 0..1023

    // ---- load this CTA's weight slice into smem (one time) ----
    {
        const int j  = tid & 7;
        const int k0 = tid >> 3;                 // 0..31
        const int cbase = cta * CPC + j;
        for (int k = k0; k < UNITS; k += 32) {
            const float* row = rk + (size_t)k * N3;
            wzs[j * 1028 + k] = row[cbase];
            wrs[j * 1028 + k] = row[cbase + UNITS];
            whs[j * 1028 + k] = row[cbase + 2 * UNITS];
        }
    }

    // ---- initialize g_h = hidden ----
    {
        int gidx = cta * TPB + tid;              // 0..32767
        g_h[gidx]         = hidden[gidx];
        g_h[gidx + 32768] = hidden[gidx + 32768];
    }
    grid_barrier();

    const float4* wz4 = (const float4*)wzs + cc * 257;
    const float4* wr4 = (const float4*)wrs + cc * 257;
    const float4* wh4 = (const float4*)whs + cc * 257;

    // staging index precompute (8 float4 per thread per chunk)
    int st_b[8], st_c[8];
#pragma unroll
    for (int i = 0; i < 8; i++) {
        int flat = i * TPB + tid;                // 0..2047
        st_b[i] = flat >> 5;                     // 0..63
        st_c[i] = flat & 31;                     // 0..31
    }

    for (int t = 0; t < TLEN; t++) {
        // =================== Phase A: m_zr = h @ W_zr, gates ===================
        {
            const float4* gh4 = (const float4*)g_h;
            float4* cur = (float4*)(sm + SM_HS);
            float4* nxt = cur + (SM_HSB / 4);

            float az0 = 0.f, az1 = 0.f, ar0 = 0.f, ar1 = 0.f;

            // preload chunk 0
#pragma unroll
            for (int i = 0; i < 8; i++)
                cur[st_b[i] * 33 + st_c[i]] = __ldcg(gh4 + st_b[i] * 256 + st_c[i]);
            __syncthreads();

            for (int kc = 0; kc < NCHUNK; kc++) {
                float4 pf[8];
                if (kc < NCHUNK - 1) {
#pragma unroll
                    for (int i = 0; i < 8; i++)
                        pf[i] = __ldcg(gh4 + st_b[i] * 256 + (kc + 1) * 32 + st_c[i]);
                }
                const float4* hb0 = cur + b0 * 33;
                const float4* hb1 = cur + b1 * 33;
                const int kb = kc * 32;
#pragma unroll 8
                for (int q = 0; q < 32; q++) {
                    float4 h0 = hb0[q], h1 = hb1[q];
                    float4 wz = wz4[kb + q], wr = wr4[kb + q];
                    az0 = fmaf(h0.x, wz.x, az0); az0 = fmaf(h0.y, wz.y, az0);
                    az0 = fmaf(h0.z, wz.z, az0); az0 = fmaf(h0.w, wz.w, az0);
                    az1 = fmaf(h1.x, wz.x, az1); az1 = fmaf(h1.y, wz.y, az1);
                    az1 = fmaf(h1.z, wz.z, az1); az1 = fmaf(h1.w, wz.w, az1);
                    ar0 = fmaf(h0.x, wr.x, ar0); ar0 = fmaf(h0.y, wr.y, ar0);
                    ar0 = fmaf(h0.z, wr.z, ar0); ar0 = fmaf(h0.w, wr.w, ar0);
                    ar1 = fmaf(h1.x, wr.x, ar1); ar1 = fmaf(h1.y, wr.y, ar1);
                    ar1 = fmaf(h1.z, wr.z, ar1); ar1 = fmaf(h1.w, wr.w, ar1);
                }
                if (kc < NCHUNK - 1) {
#pragma unroll
                    for (int i = 0; i < 8; i++)
                        nxt[st_b[i] * 33 + st_c[i]] = pf[i];
                }
                __syncthreads();
                float4* tmp = cur; cur = nxt; nxt = tmp;
            }

            // gates z, r; rh -> global
            {
                size_t xb0 = ((size_t)(b0 * TLEN + t)) * N3 + col;
                size_t xb1 = ((size_t)(b1 * TLEN + t)) * N3 + col;
                float z0 = 1.f / (1.f + expf(-(g_xproj[xb0] + az0)));
                float z1 = 1.f / (1.f + expf(-(g_xproj[xb1] + az1)));
                float r0 = 1.f / (1.f + expf(-(g_xproj[xb0 + UNITS] + ar0)));
                float r1 = 1.f / (1.f + expf(-(g_xproj[xb1 + UNITS] + ar1)));
                float h0v = __ldcg(&g_h[b0 * UNITS + col]);
                float h1v = __ldcg(&g_h[b1 * UNITS + col]);
                g_rh[b0 * UNITS + col] = r0 * h0v;
                g_rh[b1 * UNITS + col] = r1 * h1v;
                zs[b0 * 8 + cc] = z0;
                zs[b1 * 8 + cc] = z1;
            }
        }
        grid_barrier();

        // =================== Phase B: m_h = rh @ W_h, update =================
        {
            const float4* gr4 = (const float4*)g_rh;
            float4* cur = (float4*)(sm + SM_HS);
            float4* nxt = cur + (SM_HSB / 4);

            float ah0 = 0.f, ah1 = 0.f;

#pragma unroll
            for (int i = 0; i < 8; i++)
                cur[st_b[i] * 33 + st_c[i]] = __ldcg(gr4 + st_b[i] * 256 + st_c[i]);
            __syncthreads();

            for (int kc = 0; kc < NCHUNK; kc++) {
                float4 pf[8];
                if (kc < NCHUNK - 1) {
#pragma unroll
                    for (int i = 0; i < 8; i++)
                        pf[i] = __ldcg(gr4 + st_b[i] * 256 + (kc + 1) * 32 + st_c[i]);
                }
                const float4* hb0 = cur + b0 * 33;
                const float4* hb1 = cur + b1 * 33;
                const int kb = kc * 32;
#pragma unroll 8
                for (int q = 0; q < 32; q++) {
                    float4 h0 = hb0[q], h1 = hb1[q];
                    float4 wh = wh4[kb + q];
                    ah0 = fmaf(h0.x, wh.x, ah0); ah0 = fmaf(h0.y, wh.y, ah0);
                    ah0 = fmaf(h0.z, wh.z, ah0); ah0 = fmaf(h0.w, wh.w, ah0);
                    ah1 = fmaf(h1.x, wh.x, ah1); ah1 = fmaf(h1.y, wh.y, ah1);
                    ah1 = fmaf(h1.z, wh.z, ah1); ah1 = fmaf(h1.w, wh.w, ah1);
                }
                if (kc < NCHUNK - 1) {
#pragma unroll
                    for (int i = 0; i < 8; i++)
                        nxt[st_b[i] * 33 + st_c[i]] = pf[i];
                }
                __syncthreads();
                float4* tmp = cur; cur = nxt; nxt = tmp;
            }

            // candidate + update
            {
                size_t xb0 = ((size_t)(b0 * TLEN + t)) * N3 + 2 * UNITS + col;
                size_t xb1 = ((size_t)(b1 * TLEN + t)) * N3 + 2 * UNITS + col;
                float hh0 = tanhf(g_xproj[xb0] + ah0);
                float hh1 = tanhf(g_xproj[xb1] + ah1);
                float z0 = zs[b0 * 8 + cc];
                float z1 = zs[b1 * 8 + cc];
                float h0v = __ldcg(&g_h[b0 * UNITS + col]);
                float h1v = __ldcg(&g_h[b1 * UNITS + col]);
                float hn0 = z0 * h0v + (1.f - z0) * hh0;
                float hn1 = z1 * h1v + (1.f - z1) * hh1;
                g_h[b0 * UNITS + col] = hn0;
                g_h[b1 * UNITS + col] = hn1;
                out[((size_t)(b0 * TLEN + t)) * UNITS + col] = hn0;
                out[((size_t)(b1 * TLEN + t)) * UNITS + col] = hn1;
                if (t == TLEN - 1) {
                    out[(size_t)BATCH * TLEN * UNITS + (size_t)b0 * UNITS + col] = hn0;
                    out[(size_t)BATCH * TLEN * UNITS + (size_t)b1 * UNITS + col] = hn1;
                }
            }
        }
        grid_barrier();
    }
}

// ---------------------------------------------------------------------------
extern "C" void kernel_launch(void* const* d_in, const int* in_sizes, int n_in,
                              void* d_out, int out_size)
{
    const int*   x      = (const int*)d_in[0];
    const float* hidden = (const float*)d_in[1];
    const float* emb    = (const float*)d_in[2];
    const float* kern   = (const float*)d_in[3];
    const float* rk     = (const float*)d_in[4];
    const float* bias   = (const float*)d_in[5];
    float* out = (float*)d_out;

    static bool attr_set = false;
    if (!attr_set) {
        cudaFuncSetAttribute(gru_scan, cudaFuncAttributeMaxDynamicSharedMemorySize,
                             SMEM_FLOATS * sizeof(float));
        attr_set = true;
    }

    // Node 1: projection GEMM (fused embedding gather)
    xproj_kernel<<<dim3(N3 / 128, (BATCH * TLEN) / 128), 256>>>(x, emb, kern, bias);

    // Node 2: persistent GRU scan
    gru_scan<<<GRID, TPB, SMEM_FLOATS * sizeof(float)>>>(hidden, rk, out);
}

// round 3
// speedup vs baseline: 1.6318x; 1.6318x over previous
#include <cuda_runtime.h>
#include <cstdint>

#define VOCAB 32000
#define EMB   256
#define UNITS 1024
#define BATCH 64
#define TLEN  512
#define N3    3072

#define GRID  128
#define TPB   256
#define NCHUNK 8           // k chunks of 128

// -------------------- device globals (no allocation allowed) ---------------
__device__ float g_xproj[(size_t)BATCH * TLEN * N3];   // [B*T, 3U]
__device__ float g_h[BATCH * UNITS];                   // current hidden
__device__ float g_rh[BATCH * UNITS];                  // r * h
__device__ unsigned g_count = 0;
__device__ unsigned g_gen   = 0;

// -------------------- helpers ----------------------------------------------
__device__ __forceinline__ uint32_t f2tf32(float x) {
    uint32_t r;
    asm("cvt.rna.tf32.f32 %0, %1;" : "=r"(r) : "f"(x));
    return r;
}

#define MMA_TF32(d0,d1,d2,d3,a0,a1,a2,a3,b0,b1)                               \
    asm volatile(                                                             \
        "mma.sync.aligned.m16n8k8.row.col.f32.tf32.tf32.f32 "                 \
        "{%0,%1,%2,%3},{%4,%5,%6,%7},{%8,%9},{%0,%1,%2,%3};"                  \
        : "+f"(d0), "+f"(d1), "+f"(d2), "+f"(d3)                              \
        : "r"(a0), "r"(a1), "r"(a2), "r"(a3), "r"(b0), "r"(b1))

// -------------------- grid barrier (all GRID CTAs co-resident) -------------
__device__ __forceinline__ void grid_barrier()
{
    __syncthreads();
    if (threadIdx.x == 0) {
        __threadfence();
        volatile unsigned* vgen = &g_gen;
        unsigned target = *vgen + 1u;
        unsigned old = atomicAdd(&g_count, 1u);
        if (old == GRID - 1u) {
            *((volatile unsigned*)&g_count) = 0u;
            __threadfence();
            *vgen = target;
        } else {
            while (*vgen != target) __nanosleep(64);
        }
    }
    __syncthreads();
}

// ---------------------------------------------------------------------------
// Kernel 1: xproj = gather(emb_table, x) @ kernel + bias   (unchanged, verified)
// ---------------------------------------------------------------------------
__global__ __launch_bounds__(256) void xproj_kernel(
    const int* __restrict__ x,
    const float* __restrict__ emb_table,
    const float* __restrict__ kernelW,
    const float* __restrict__ bias)
{
    __shared__ __align__(16) float As[16][128];
    __shared__ __align__(16) float Bs[16][128];

    const int tid = threadIdx.x;
    const int m0 = blockIdx.y * 128;
    const int n0 = blockIdx.x * 128;

    const int arow = tid & 127;
    const int kq0  = tid >> 7;
    const int token = x[m0 + arow];
    const float* aptr = emb_table + (size_t)token * EMB;

    const int bk = tid >> 4;
    const int bq = tid & 15;
    const int ty = tid >> 4;
    const int tx = tid & 15;

    float acc[8][8];
#pragma unroll
    for (int i = 0; i < 8; i++)
#pragma unroll
        for (int j = 0; j < 8; j++) acc[i][j] = 0.f;

    for (int k0 = 0; k0 < EMB; k0 += 16) {
        float4 va0 = *(const float4*)(aptr + k0 + kq0 * 4);
        float4 va1 = *(const float4*)(aptr + k0 + (kq0 + 2) * 4);
        const float* wrow = kernelW + (size_t)(k0 + bk) * N3 + n0;
        float4 vb0 = *(const float4*)(wrow + bq * 4);
        float4 vb1 = *(const float4*)(wrow + bq * 4 + 64);

        __syncthreads();
        As[kq0 * 4 + 0][arow] = va0.x;
        As[kq0 * 4 + 1][arow] = va0.y;
        As[kq0 * 4 + 2][arow] = va0.z;
        As[kq0 * 4 + 3][arow] = va0.w;
        As[(kq0 + 2) * 4 + 0][arow] = va1.x;
        As[(kq0 + 2) * 4 + 1][arow] = va1.y;
        As[(kq0 + 2) * 4 + 2][arow] = va1.z;
        As[(kq0 + 2) * 4 + 3][arow] = va1.w;
        Bs[bk][bq * 4 + 0] = vb0.x;
        Bs[bk][bq * 4 + 1] = vb0.y;
        Bs[bk][bq * 4 + 2] = vb0.z;
        Bs[bk][bq * 4 + 3] = vb0.w;
        Bs[bk][bq * 4 + 64] = vb1.x;
        Bs[bk][bq * 4 + 65] = vb1.y;
        Bs[bk][bq * 4 + 66] = vb1.z;
        Bs[bk][bq * 4 + 67] = vb1.w;
        __syncthreads();

#pragma unroll
        for (int k = 0; k < 16; k++) {
            float4 a0 = *(const float4*)(&As[k][ty * 8]);
            float4 a1 = *(const float4*)(&As[k][ty * 8 + 4]);
            float4 b0 = *(const float4*)(&Bs[k][tx * 8]);
            float4 b1 = *(const float4*)(&Bs[k][tx * 8 + 4]);
            float av[8] = {a0.x, a0.y, a0.z, a0.w, a1.x, a1.y, a1.z, a1.w};
            float bv[8] = {b0.x, b0.y, b0.z, b0.w, b1.x, b1.y, b1.z, b1.w};
#pragma unroll
            for (int i = 0; i < 8; i++)
#pragma unroll
                for (int j = 0; j < 8; j++)
                    acc[i][j] = fmaf(av[i], bv[j], acc[i][j]);
        }
    }

#pragma unroll
    for (int i = 0; i < 8; i++) {
        const int row = m0 + ty * 8 + i;
        float* dst = &g_xproj[(size_t)row * N3 + n0 + tx * 8];
        const float* bptr = bias + n0 + tx * 8;
        float4 o0, o1;
        o0.x = acc[i][0] + bptr[0];
        o0.y = acc[i][1] + bptr[1];
        o0.z = acc[i][2] + bptr[2];
        o0.w = acc[i][3] + bptr[3];
        o1.x = acc[i][4] + bptr[4];
        o1.y = acc[i][5] + bptr[5];
        o1.z = acc[i][6] + bptr[6];
        o1.w = acc[i][7] + bptr[7];
        *(float4*)dst = o0;
        *(float4*)(dst + 4) = o1;
    }
}

// ---------------------------------------------------------------------------
// Kernel 2: persistent GRU scan, tf32 mma.sync.
// CTA c owns units [c*8, c*8+8). SMEM (floats):
//   ws  [24][1028]  @ 0      rows 0-7: Wz cols, 8-15: Wr cols, 16-23: Wh cols (tf32)
//   hs  [2][64][132] @ 24672 staged h/rh chunks, tf32 patterns
//   pacc[8][512]    @ 41568  per-warp partial C
//   zs  [64][8]     @ 45664  z gate
// total 46176 floats = 184704 B
// ---------------------------------------------------------------------------
#define SM_WS   0
#define SM_HS   24672
#define SM_HSB  8448
#define SM_PACC 41568
#define SM_ZS   45664
#define SMEM_FLOATS 46176

__global__ void __launch_bounds__(TPB, 1) gru_scan(
    const float* __restrict__ hidden,
    const float* __restrict__ rk,
    float* __restrict__ out)
{
    extern __shared__ float sm[];
    uint32_t* smu = (uint32_t*)sm;
    float* pacc = sm + SM_PACC;
    float* zs   = sm + SM_ZS;

    const int tid  = threadIdx.x;
    const int cta  = blockIdx.x;
    const int wid  = tid >> 5;
    const int lane = tid & 31;
    const int gID  = lane >> 2;       // 0..7
    const int tig  = lane & 3;        // 0..3
    const int mg   = wid & 1;         // m-group: rows [mg*32, mg*32+32)
    const int ksl  = wid >> 1;        // k-slice 0..3 (k-tiles ksl*4..ksl*4+4 per chunk)

    // ---- load weight slice to smem as tf32 (one time) ----
    for (int idx = tid; idx < 24 * 1024; idx += TPB) {
        const int r = idx >> 10;            // ws row 0..23
        const int k = idx & 1023;
        const int col = (r >> 3) * UNITS + cta * 8 + (r & 7);
        smu[SM_WS + r * 1028 + k] = f2tf32(rk[(size_t)k * N3 + col]);
    }

    // ---- initialize g_h ----
    {
        int gidx = cta * TPB + tid;
        g_h[gidx]         = hidden[gidx];
        g_h[gidx + 32768] = hidden[gidx + 32768];
    }
    grid_barrier();

    // staging index precompute (8 float4 per thread per 128-k chunk)
    int st_b[8], st_c[8];
#pragma unroll
    for (int i = 0; i < 8; i++) {
        int flat = i * TPB + tid;
        st_b[i] = flat >> 5;
        st_c[i] = flat & 31;
    }

    const int r0 = mg * 32 + gID;   // A-frag base row

    for (int t = 0; t < TLEN; t++) {
        // =================== Phase A: zr = h @ [Wz|Wr] =======================
        {
            const float4* gh4 = (const float4*)g_h;
            int buf = 0;

            float az[2][4], ar[2][4];
#pragma unroll
            for (int m = 0; m < 2; m++)
#pragma unroll
                for (int c = 0; c < 4; c++) { az[m][c] = 0.f; ar[m][c] = 0.f; }

            // preload chunk 0 (with tf32 rounding)
#pragma unroll
            for (int i = 0; i < 8; i++) {
                float4 v = __ldcg(gh4 + st_b[i] * 256 + st_c[i]);
                uint4 w = make_uint4(f2tf32(v.x), f2tf32(v.y), f2tf32(v.z), f2tf32(v.w));
                *(uint4*)&smu[SM_HS + st_b[i] * 132 + st_c[i] * 4] = w;
            }
            __syncthreads();

            for (int kc = 0; kc < NCHUNK; kc++) {
                float4 pf[8];
                if (kc < NCHUNK - 1) {
#pragma unroll
                    for (int i = 0; i < 8; i++)
                        pf[i] = __ldcg(gh4 + st_b[i] * 256 + (kc + 1) * 32 + st_c[i]);
                }

                const uint32_t* hb = &smu[SM_HS + buf * SM_HSB];
                const int kg = kc * 128;
#pragma unroll
                for (int i = 0; i < 4; i++) {
                    const int kb = (ksl * 4 + i) * 8;
                    uint32_t a00 = hb[(r0     ) * 132 + kb + tig];
                    uint32_t a01 = hb[(r0 +  8) * 132 + kb + tig];
                    uint32_t a02 = hb[(r0     ) * 132 + kb + tig + 4];
                    uint32_t a03 = hb[(r0 +  8) * 132 + kb + tig + 4];
                    uint32_t a10 = hb[(r0 + 16) * 132 + kb + tig];
                    uint32_t a11 = hb[(r0 + 24) * 132 + kb + tig];
                    uint32_t a12 = hb[(r0 + 16) * 132 + kb + tig + 4];
                    uint32_t a13 = hb[(r0 + 24) * 132 + kb + tig + 4];
                    uint32_t bz0 = smu[SM_WS + gID * 1028 + kg + kb + tig];
                    uint32_t bz1 = smu[SM_WS + gID * 1028 + kg + kb + tig + 4];
                    uint32_t br0 = smu[SM_WS + (8 + gID) * 1028 + kg + kb + tig];
                    uint32_t br1 = smu[SM_WS + (8 + gID) * 1028 + kg + kb + tig + 4];
                    MMA_TF32(az[0][0], az[0][1], az[0][2], az[0][3], a00, a01, a02, a03, bz0, bz1);
                    MMA_TF32(az[1][0], az[1][1], az[1][2], az[1][3], a10, a11, a12, a13, bz0, bz1);
                    MMA_TF32(ar[0][0], ar[0][1], ar[0][2], ar[0][3], a00, a01, a02, a03, br0, br1);
                    MMA_TF32(ar[1][0], ar[1][1], ar[1][2], ar[1][3], a10, a11, a12, a13, br0, br1);
                }

                if (kc < NCHUNK - 1) {
#pragma unroll
                    for (int i = 0; i < 8; i++) {
                        float4 v = pf[i];
                        uint4 w = make_uint4(f2tf32(v.x), f2tf32(v.y), f2tf32(v.z), f2tf32(v.w));
                        *(uint4*)&smu[SM_HS + (buf ^ 1) * SM_HSB + st_b[i] * 132 + st_c[i] * 4] = w;
                    }
                }
                __syncthreads();
                buf ^= 1;
            }

            // store warp partials: C[32x16] -> pacc[wid][lrow*16 + lcol]
            float* pw = pacc + wid * 512;
#pragma unroll
            for (int m = 0; m < 2; m++) {
                const int rb = m * 16;
                pw[(rb + gID    ) * 16 + 2 * tig    ] = az[m][0];
                pw[(rb + gID    ) * 16 + 2 * tig + 1] = az[m][1];
                pw[(rb + gID + 8) * 16 + 2 * tig    ] = az[m][2];
                pw[(rb + gID + 8) * 16 + 2 * tig + 1] = az[m][3];
                pw[(rb + gID    ) * 16 + 8 + 2 * tig    ] = ar[m][0];
                pw[(rb + gID    ) * 16 + 8 + 2 * tig + 1] = ar[m][1];
                pw[(rb + gID + 8) * 16 + 8 + 2 * tig    ] = ar[m][2];
                pw[(rb + gID + 8) * 16 + 8 + 2 * tig + 1] = ar[m][3];
            }
            __syncthreads();

            // gates: 512 elements, 2 per thread
#pragma unroll
            for (int e = 0; e < 2; e++) {
                const int idx = e * TPB + tid;
                const int row = idx >> 3;
                const int u   = idx & 7;
                const int rmg = row >> 5;
                const int lr  = row & 31;
                float zp = 0.f, rp = 0.f;
#pragma unroll
                for (int s = 0; s < 4; s++) {
                    const float* p = pacc + (s * 2 + rmg) * 512 + lr * 16;
                    zp += p[u];
                    rp += p[8 + u];
                }
                const int col = cta * 8 + u;
                const size_t xb = ((size_t)(row * TLEN + t)) * N3 + col;
                float z = 1.f / (1.f + expf(-(g_xproj[xb] + zp)));
                float r = 1.f / (1.f + expf(-(g_xproj[xb + UNITS] + rp)));
                float hv = g_h[row * UNITS + col];
                g_rh[row * UNITS + col] = r * hv;
                zs[row * 8 + u] = z;
            }
        }
        grid_barrier();

        // =================== Phase B: m_h = rh @ Wh ==========================
        {
            const float4* gr4 = (const float4*)g_rh;
            int buf = 0;

            float ah[2][4];
#pragma unroll
            for (int m = 0; m < 2; m++)
#pragma unroll
                for (int c = 0; c < 4; c++) ah[m][c] = 0.f;

#pragma unroll
            for (int i = 0; i < 8; i++) {
                float4 v = __ldcg(gr4 + st_b[i] * 256 + st_c[i]);
                uint4 w = make_uint4(f2tf32(v.x), f2tf32(v.y), f2tf32(v.z), f2tf32(v.w));
                *(uint4*)&smu[SM_HS + st_b[i] * 132 + st_c[i] * 4] = w;
            }
            __syncthreads();

            for (int kc = 0; kc < NCHUNK; kc++) {
                float4 pf[8];
                if (kc < NCHUNK - 1) {
#pragma unroll
                    for (int i = 0; i < 8; i++)
                        pf[i] = __ldcg(gr4 + st_b[i] * 256 + (kc + 1) * 32 + st_c[i]);
                }

                const uint32_t* hb = &smu[SM_HS + buf * SM_HSB];
                const int kg = kc * 128;
#pragma unroll
                for (int i = 0; i < 4; i++) {
                    const int kb = (ksl * 4 + i) * 8;
                    uint32_t a00 = hb[(r0     ) * 132 + kb + tig];
                    uint32_t a01 = hb[(r0 +  8) * 132 + kb + tig];
                    uint32_t a02 = hb[(r0     ) * 132 + kb + tig + 4];
                    uint32_t a03 = hb[(r0 +  8) * 132 + kb + tig + 4];
                    uint32_t a10 = hb[(r0 + 16) * 132 + kb + tig];
                    uint32_t a11 = hb[(r0 + 24) * 132 + kb + tig];
                    uint32_t a12 = hb[(r0 + 16) * 132 + kb + tig + 4];
                    uint32_t a13 = hb[(r0 + 24) * 132 + kb + tig + 4];
                    uint32_t bh0 = smu[SM_WS + (16 + gID) * 1028 + kg + kb + tig];
                    uint32_t bh1 = smu[SM_WS + (16 + gID) * 1028 + kg + kb + tig + 4];
                    MMA_TF32(ah[0][0], ah[0][1], ah[0][2], ah[0][3], a00, a01, a02, a03, bh0, bh1);
                    MMA_TF32(ah[1][0], ah[1][1], ah[1][2], ah[1][3], a10, a11, a12, a13, bh0, bh1);
                }

                if (kc < NCHUNK - 1) {
#pragma unroll
                    for (int i = 0; i < 8; i++) {
                        float4 v = pf[i];
                        uint4 w = make_uint4(f2tf32(v.x), f2tf32(v.y), f2tf32(v.z), f2tf32(v.w));
                        *(uint4*)&smu[SM_HS + (buf ^ 1) * SM_HSB + st_b[i] * 132 + st_c[i] * 4] = w;
                    }
                }
                __syncthreads();
                buf ^= 1;
            }

            // store warp partials: C[32x8] -> pacc[wid][lrow*8 + lcol]
            float* pw = pacc + wid * 256;
#pragma unroll
            for (int m = 0; m < 2; m++) {
                const int rb = m * 16;
                pw[(rb + gID    ) * 8 + 2 * tig    ] = ah[m][0];
                pw[(rb + gID    ) * 8 + 2 * tig + 1] = ah[m][1];
                pw[(rb + gID + 8) * 8 + 2 * tig    ] = ah[m][2];
                pw[(rb + gID + 8) * 8 + 2 * tig + 1] = ah[m][3];
            }
            __syncthreads();

            // h update: 512 elements, 2 per thread
#pragma unroll
            for (int e = 0; e < 2; e++) {
                const int idx = e * TPB + tid;
                const int row = idx >> 3;
                const int u   = idx & 7;
                const int rmg = row >> 5;
                const int lr  = row & 31;
                float mp = 0.f;
#pragma unroll
                for (int s = 0; s < 4; s++)
                    mp += pacc[(s * 2 + rmg) * 256 + lr * 8 + u];

                const int col = cta * 8 + u;
                const size_t xb = ((size_t)(row * TLEN + t)) * N3 + 2 * UNITS + col;
                float hh = tanhf(g_xproj[xb] + mp);
                float z  = zs[row * 8 + u];
                float hv = g_h[row * UNITS + col];
                float hn = z * hv + (1.f - z) * hh;
                g_h[row * UNITS + col] = hn;
                out[((size_t)(row * TLEN + t)) * UNITS + col] = hn;
                if (t == TLEN - 1)
                    out[(size_t)BATCH * TLEN * UNITS + (size_t)row * UNITS + col] = hn;
            }
        }
        grid_barrier();
    }
}

// ---------------------------------------------------------------------------
extern "C" void kernel_launch(void* const* d_in, const int* in_sizes, int n_in,
                              void* d_out, int out_size)
{
    const int*   x      = (const int*)d_in[0];
    const float* hidden = (const float*)d_in[1];
    const float* emb    = (const float*)d_in[2];
    const float* kern   = (const float*)d_in[3];
    const float* rk     = (const float*)d_in[4];
    const float* bias   = (const float*)d_in[5];
    float* out = (float*)d_out;

    static bool attr_set = false;
    if (!attr_set) {
        cudaFuncSetAttribute(gru_scan, cudaFuncAttributeMaxDynamicSharedMemorySize,
                             SMEM_FLOATS * sizeof(float));
        attr_set = true;
    }

    // Node 1: projection GEMM (fused embedding gather)
    xproj_kernel<<<dim3(N3 / 128, (BATCH * TLEN) / 128), 256>>>(x, emb, kern, bias);

    // Node 2: persistent GRU scan (tf32 tensor cores)
    gru_scan<<<GRID, TPB, SMEM_FLOATS * sizeof(float)>>>(hidden, rk, out);
}

// round 4
// speedup vs baseline: 1.8278x; 1.1201x over previous
#include <cuda_runtime.h>
#include <cstdint>

#define VOCAB 32000
#define EMB   256
#define UNITS 1024
#define BATCH 64
#define TLEN  512
#define N3    3072

#define GRID  128
#define TPB   512
#define NCHUNK 8           // k chunks of 128

// -------------------- device globals (no allocation allowed) ---------------
__device__ float g_xproj[(size_t)BATCH * TLEN * N3];            // [B*T, 3U]
__device__ __align__(16) uint32_t g_hx[BATCH * UNITS];          // h  (tf32 bits)
__device__ __align__(16) uint32_t g_rhx[BATCH * UNITS];         // r*h (tf32 bits)
__device__ unsigned g_count = 0;
__device__ unsigned g_gen   = 0;

// -------------------- helpers ----------------------------------------------
__device__ __forceinline__ uint32_t f2tf32(float x) {
    uint32_t r;
    asm("cvt.rna.tf32.f32 %0, %1;" : "=r"(r) : "f"(x));
    return r;
}

__device__ __forceinline__ uint32_t s2u(const void* p) {
    uint32_t a;
    asm("{ .reg .u64 t; cvta.to.shared.u64 t, %1; cvt.u32.u64 %0, t; }"
        : "=r"(a) : "l"(p));
    return a;
}

__device__ __forceinline__ void cp_async16(uint32_t saddr, const void* gaddr) {
    asm volatile("cp.async.cg.shared.global [%0], [%1], 16;"
                 :: "r"(saddr), "l"(gaddr));
}
#define CP_COMMIT() asm volatile("cp.async.commit_group;")
#define CP_WAIT0()  asm volatile("cp.async.wait_group 0;")

#define MMA_TF32(d0,d1,d2,d3,a0,a1,a2,a3,b0,b1)                               \
    asm volatile(                                                             \
        "mma.sync.aligned.m16n8k8.row.col.f32.tf32.tf32.f32 "                 \
        "{%0,%1,%2,%3},{%4,%5,%6,%7},{%8,%9},{%0,%1,%2,%3};"                  \
        : "+f"(d0), "+f"(d1), "+f"(d2), "+f"(d3)                              \
        : "r"(a0), "r"(a1), "r"(a2), "r"(a3), "r"(b0), "r"(b1))

// -------------------- grid barrier (all GRID CTAs co-resident) -------------
__device__ __forceinline__ void grid_barrier()
{
    __syncthreads();
    if (threadIdx.x == 0) {
        __threadfence();
        volatile unsigned* vgen = &g_gen;
        unsigned target = *vgen + 1u;
        unsigned old = atomicAdd(&g_count, 1u);
        if (old == GRID - 1u) {
            *((volatile unsigned*)&g_count) = 0u;
            __threadfence();
            *vgen = target;
        } else {
            while (*vgen != target) __nanosleep(32);
        }
    }
    __syncthreads();
}

// ---------------------------------------------------------------------------
// Kernel 1: xproj = gather(emb_table, x) @ kernel + bias  — tf32 mma.sync
// C[32768, 3072], K=256. CTA tile 128x128, 256 threads (8 warps: 2m x 4n),
// warp tile m64 x n32. A gathered from emb rows.
// ---------------------------------------------------------------------------
__global__ __launch_bounds__(256) void xproj_tf32(
    const int* __restrict__ x,
    const float* __restrict__ emb_table,
    const float* __restrict__ kernelW,
    const float* __restrict__ bias)
{
    __shared__ uint32_t As[128 * 20];   // [m][k16] pad->20
    __shared__ uint32_t Bs[128 * 20];   // [n][k16] pad->20

    const int tid  = threadIdx.x;
    const int wid  = tid >> 5;
    const int lane = tid & 31;
    const int gID  = lane >> 2;
    const int tig  = lane & 3;
    const int wm   = wid & 1;          // 0..1 -> rows wm*64
    const int wn   = wid >> 1;         // 0..3 -> cols wn*32

    const int m0 = blockIdx.y * 128;
    const int n0 = blockIdx.x * 128;

    // A gather: one emb row per (tid&127), k-halves by tid>>7
    const int arow = tid & 127;
    const int akq  = tid >> 7;          // 0/1 -> k offset 8*akq
    const int token = x[m0 + arow];
    const float* aptr = emb_table + (size_t)token * EMB;

    // B load: rows k (tid>>4), 8 cols per thread (tid&15)
    const int bk = tid >> 4;
    const int bq = tid & 15;

    float acc[4][4][4];
#pragma unroll
    for (int mi = 0; mi < 4; mi++)
#pragma unroll
        for (int ni = 0; ni < 4; ni++)
#pragma unroll
            for (int c = 0; c < 4; c++) acc[mi][ni][c] = 0.f;

    for (int k0 = 0; k0 < EMB; k0 += 16) {
        float4 a0 = *(const float4*)(aptr + k0 + akq * 8);
        float4 a1 = *(const float4*)(aptr + k0 + akq * 8 + 4);
        const float* wr = kernelW + (size_t)(k0 + bk) * N3 + n0 + bq * 8;
        float4 b0 = *(const float4*)wr;
        float4 b1 = *(const float4*)(wr + 4);

        __syncthreads();
        uint32_t* ad = &As[arow * 20 + akq * 8];
        ad[0] = f2tf32(a0.x); ad[1] = f2tf32(a0.y);
        ad[2] = f2tf32(a0.z); ad[3] = f2tf32(a0.w);
        ad[4] = f2tf32(a1.x); ad[5] = f2tf32(a1.y);
        ad[6] = f2tf32(a1.z); ad[7] = f2tf32(a1.w);
        Bs[(bq * 8 + 0) * 20 + bk] = f2tf32(b0.x);
        Bs[(bq * 8 + 1) * 20 + bk] = f2tf32(b0.y);
        Bs[(bq * 8 + 2) * 20 + bk] = f2tf32(b0.z);
        Bs[(bq * 8 + 3) * 20 + bk] = f2tf32(b0.w);
        Bs[(bq * 8 + 4) * 20 + bk] = f2tf32(b1.x);
        Bs[(bq * 8 + 5) * 20 + bk] = f2tf32(b1.y);
        Bs[(bq * 8 + 6) * 20 + bk] = f2tf32(b1.z);
        Bs[(bq * 8 + 7) * 20 + bk] = f2tf32(b1.w);
        __syncthreads();

#pragma unroll
        for (int kt = 0; kt < 2; kt++) {
            const int kb = kt * 8;
            uint32_t af[4][4], bf[4][2];
#pragma unroll
            for (int mi = 0; mi < 4; mi++) {
                const int mr = wm * 64 + mi * 16;
                af[mi][0] = As[(mr + gID    ) * 20 + kb + tig];
                af[mi][1] = As[(mr + gID + 8) * 20 + kb + tig];
                af[mi][2] = As[(mr + gID    ) * 20 + kb + tig + 4];
                af[mi][3] = As[(mr + gID + 8) * 20 + kb + tig + 4];
            }
#pragma unroll
            for (int ni = 0; ni < 4; ni++) {
                const int nb = wn * 32 + ni * 8;
                bf[ni][0] = Bs[(nb + gID) * 20 + kb + tig];
                bf[ni][1] = Bs[(nb + gID) * 20 + kb + tig + 4];
            }
#pragma unroll
            for (int mi = 0; mi < 4; mi++)
#pragma unroll
                for (int ni = 0; ni < 4; ni++)
                    MMA_TF32(acc[mi][ni][0], acc[mi][ni][1],
                             acc[mi][ni][2], acc[mi][ni][3],
                             af[mi][0], af[mi][1], af[mi][2], af[mi][3],
                             bf[ni][0], bf[ni][1]);
        }
    }

    // epilogue: bias + store
#pragma unroll
    for (int mi = 0; mi < 4; mi++) {
#pragma unroll
        for (int ni = 0; ni < 4; ni++) {
            const int row = m0 + wm * 64 + mi * 16 + gID;
            const int col = n0 + wn * 32 + ni * 8 + 2 * tig;
            const float bz0 = bias[col], bz1 = bias[col + 1];
            float2 v0 = make_float2(acc[mi][ni][0] + bz0, acc[mi][ni][1] + bz1);
            float2 v1 = make_float2(acc[mi][ni][2] + bz0, acc[mi][ni][3] + bz1);
            *(float2*)&g_xproj[(size_t)row * N3 + col]       = v0;
            *(float2*)&g_xproj[(size_t)(row + 8) * N3 + col] = v1;
        }
    }
}

// ---------------------------------------------------------------------------
// Kernel 2: persistent GRU scan, tf32 mma, 512 threads (16 warps),
// cp.async staging of pre-rounded tf32 h/rh broadcast.
// CTA c owns units [c*8, c*8+8).
// SMEM (floats):
//   ws   [24][1028]      @ 0       Wz/Wr/Wh cols (tf32 bits)
//   hs   [2][64][132]    @ 24672   staged h/rh chunks (tf32 bits)
//   pacc [16][544|288]   @ 41568   per-warp partial C (A: 32x16 s17, B: 32x8 s9)
//   zs   [512]           @ 50272
//   hloc [512]           @ 50784   exact fp32 h for own columns
// total 51296 floats = 205184 B
// ---------------------------------------------------------------------------
#define SM_WS   0
#define SM_HS   24672
#define SM_HSB  8448
#define SM_PACC 41568
#define SM_ZS   50272
#define SM_HLOC 50784
#define SMEM_FLOATS 51296

__global__ void __launch_bounds__(TPB, 1) gru_scan(
    const float* __restrict__ hidden,
    const float* __restrict__ rk,
    float* __restrict__ out)
{
    extern __shared__ float sm[];
    uint32_t* smu = (uint32_t*)sm;
    float* pacc = sm + SM_PACC;
    float* zs   = sm + SM_ZS;
    float* hloc = sm + SM_HLOC;

    const int tid  = threadIdx.x;
    const int cta  = blockIdx.x;
    const int wid  = tid >> 5;
    const int lane = tid & 31;
    const int gID  = lane >> 2;
    const int tig  = lane & 3;
    const int mg   = wid & 1;         // m-group: rows [mg*32, mg*32+32)
    const int ksl  = wid >> 1;        // k-slice 0..7 (2 k-tiles per 128-chunk)
    const int r0   = mg * 32 + gID;

    // epilogue mapping
    const int erow = tid >> 3;        // batch row 0..63
    const int eu   = tid & 7;         // local unit
    const int ecol = cta * 8 + eu;
    const int ermg = erow >> 5;
    const int elr  = erow & 31;

    // ---- load weight slice to smem as tf32 (one time) ----
    for (int idx = tid; idx < 24 * 1024; idx += TPB) {
        const int r = idx >> 10;
        const int k = idx & 1023;
        const int col = (r >> 3) * UNITS + cta * 8 + (r & 7);
        smu[SM_WS + r * 1028 + k] = f2tf32(rk[(size_t)k * N3 + col]);
    }

    // ---- init g_hx (tf32 of hidden) + hloc (exact own columns) ----
    {
        int gidx = cta * TPB + tid;              // covers 64*1024 exactly
        g_hx[gidx] = f2tf32(hidden[gidx]);
        hloc[tid]  = hidden[erow * UNITS + ecol];
    }
    grid_barrier();

    // staging: 4 x 16B per thread per 128-k chunk
    int st_b[4], st_c[4];
    uint32_t st_s[4];
#pragma unroll
    for (int i = 0; i < 4; i++) {
        int flat = i * TPB + tid;               // 0..2047
        st_b[i] = flat >> 5;                    // row 0..63
        st_c[i] = flat & 31;                    // 16B slot 0..31
        st_s[i] = s2u(&smu[SM_HS + st_b[i] * 132 + st_c[i] * 4]);
    }

    for (int t = 0; t < TLEN; t++) {
        // =================== Phase A: zr = h @ [Wz|Wr] =======================
        {
            const uint32_t* src = g_hx;
            int buf = 0;

            float az[2][4], ar[2][4];
#pragma unroll
            for (int m = 0; m < 2; m++)
#pragma unroll
                for (int c = 0; c < 4; c++) { az[m][c] = 0.f; ar[m][c] = 0.f; }

            // prologue: stage chunk 0
#pragma unroll
            for (int i = 0; i < 4; i++)
                cp_async16(st_s[i], src + st_b[i] * 1024 + st_c[i] * 4);
            CP_COMMIT();

            for (int kc = 0; kc < NCHUNK; kc++) {
                CP_WAIT0();
                __syncthreads();
                if (kc < NCHUNK - 1) {
#pragma unroll
                    for (int i = 0; i < 4; i++)
                        cp_async16(st_s[i] + (buf ^ 1) * (SM_HSB * 4),
                                   src + st_b[i] * 1024 + (kc + 1) * 128 + st_c[i] * 4);
                    CP_COMMIT();
                }

                const uint32_t* hb = &smu[SM_HS + buf * SM_HSB];
                const int kg = kc * 128;
#pragma unroll
                for (int i = 0; i < 2; i++) {
                    const int kb = (ksl * 2 + i) * 8;
                    uint32_t a00 = hb[(r0     ) * 132 + kb + tig];
                    uint32_t a01 = hb[(r0 +  8) * 132 + kb + tig];
                    uint32_t a02 = hb[(r0     ) * 132 + kb + tig + 4];
                    uint32_t a03 = hb[(r0 +  8) * 132 + kb + tig + 4];
                    uint32_t a10 = hb[(r0 + 16) * 132 + kb + tig];
                    uint32_t a11 = hb[(r0 + 24) * 132 + kb + tig];
                    uint32_t a12 = hb[(r0 + 16) * 132 + kb + tig + 4];
                    uint32_t a13 = hb[(r0 + 24) * 132 + kb + tig + 4];
                    uint32_t bz0 = smu[SM_WS + gID * 1028 + kg + kb + tig];
                    uint32_t bz1 = smu[SM_WS + gID * 1028 + kg + kb + tig + 4];
                    uint32_t br0 = smu[SM_WS + (8 + gID) * 1028 + kg + kb + tig];
                    uint32_t br1 = smu[SM_WS + (8 + gID) * 1028 + kg + kb + tig + 4];
                    MMA_TF32(az[0][0], az[0][1], az[0][2], az[0][3], a00, a01, a02, a03, bz0, bz1);
                    MMA_TF32(az[1][0], az[1][1], az[1][2], az[1][3], a10, a11, a12, a13, bz0, bz1);
                    MMA_TF32(ar[0][0], ar[0][1], ar[0][2], ar[0][3], a00, a01, a02, a03, br0, br1);
                    MMA_TF32(ar[1][0], ar[1][1], ar[1][2], ar[1][3], a10, a11, a12, a13, br0, br1);
                }
                buf ^= 1;
            }

            // store warp partials: C[32x16], row stride 17
            float* pw = pacc + wid * 544;
#pragma unroll
            for (int m = 0; m < 2; m++) {
                const int rb = m * 16;
                pw[(rb + gID    ) * 17 + 2 * tig    ] = az[m][0];
                pw[(rb + gID    ) * 17 + 2 * tig + 1] = az[m][1];
                pw[(rb + gID + 8) * 17 + 2 * tig    ] = az[m][2];
                pw[(rb + gID + 8) * 17 + 2 * tig + 1] = az[m][3];
                pw[(rb + gID    ) * 17 + 8 + 2 * tig    ] = ar[m][0];
                pw[(rb + gID    ) * 17 + 8 + 2 * tig + 1] = ar[m][1];
                pw[(rb + gID + 8) * 17 + 8 + 2 * tig    ] = ar[m][2];
                pw[(rb + gID + 8) * 17 + 8 + 2 * tig + 1] = ar[m][3];
            }
            __syncthreads();

            // gates: 512 outputs, 1 per thread; reduce 8 k-slices
            {
                float zp = 0.f, rp = 0.f;
#pragma unroll
                for (int s = 0; s < 8; s++) {
                    const float* p = pacc + (s * 2 + ermg) * 544 + elr * 17;
                    zp += p[eu];
                    rp += p[8 + eu];
                }
                const size_t xb = ((size_t)(erow * TLEN + t)) * N3 + ecol;
                float z = 1.f / (1.f + expf(-(g_xproj[xb] + zp)));
                float r = 1.f / (1.f + expf(-(g_xproj[xb + UNITS] + rp)));
                float hv = hloc[tid];
                g_rhx[erow * UNITS + ecol] = f2tf32(r * hv);
                zs[tid] = z;
            }
        }
        grid_barrier();

        // =================== Phase B: m_h = rh @ Wh ==========================
        {
            const uint32_t* src = g_rhx;
            int buf = 0;

            float ah[2][4];
#pragma unroll
            for (int m = 0; m < 2; m++)
#pragma unroll
                for (int c = 0; c < 4; c++) ah[m][c] = 0.f;

#pragma unroll
            for (int i = 0; i < 4; i++)
                cp_async16(st_s[i], src + st_b[i] * 1024 + st_c[i] * 4);
            CP_COMMIT();

            for (int kc = 0; kc < NCHUNK; kc++) {
                CP_WAIT0();
                __syncthreads();
                if (kc < NCHUNK - 1) {
#pragma unroll
                    for (int i = 0; i < 4; i++)
                        cp_async16(st_s[i] + (buf ^ 1) * (SM_HSB * 4),
                                   src + st_b[i] * 1024 + (kc + 1) * 128 + st_c[i] * 4);
                    CP_COMMIT();
                }

                const uint32_t* hb = &smu[SM_HS + buf * SM_HSB];
                const int kg = kc * 128;
#pragma unroll
                for (int i = 0; i < 2; i++) {
                    const int kb = (ksl * 2 + i) * 8;
                    uint32_t a00 = hb[(r0     ) * 132 + kb + tig];
                    uint32_t a01 = hb[(r0 +  8) * 132 + kb + tig];
                    uint32_t a02 = hb[(r0     ) * 132 + kb + tig + 4];
                    uint32_t a03 = hb[(r0 +  8) * 132 + kb + tig + 4];
                    uint32_t a10 = hb[(r0 + 16) * 132 + kb + tig];
                    uint32_t a11 = hb[(r0 + 24) * 132 + kb + tig];
                    uint32_t a12 = hb[(r0 + 16) * 132 + kb + tig + 4];
                    uint32_t a13 = hb[(r0 + 24) * 132 + kb + tig + 4];
                    uint32_t bh0 = smu[SM_WS + (16 + gID) * 1028 + kg + kb + tig];
                    uint32_t bh1 = smu[SM_WS + (16 + gID) * 1028 + kg + kb + tig + 4];
                    MMA_TF32(ah[0][0], ah[0][1], ah[0][2], ah[0][3], a00, a01, a02, a03, bh0, bh1);
                    MMA_TF32(ah[1][0], ah[1][1], ah[1][2], ah[1][3], a10, a11, a12, a13, bh0, bh1);
                }
                buf ^= 1;
            }

            // store warp partials: C[32x8], row stride 9
            float* pw = pacc + wid * 288;
#pragma unroll
            for (int m = 0; m < 2; m++) {
                const int rb = m * 16;
                pw[(rb + gID    ) * 9 + 2 * tig    ] = ah[m][0];
                pw[(rb + gID    ) * 9 + 2 * tig + 1] = ah[m][1];
                pw[(rb + gID + 8) * 9 + 2 * tig    ] = ah[m][2];
                pw[(rb + gID + 8) * 9 + 2 * tig + 1] = ah[m][3];
            }
            __syncthreads();

            // h update: 512 outputs, 1 per thread
            {
                float mp = 0.f;
#pragma unroll
                for (int s = 0; s < 8; s++)
                    mp += pacc[(s * 2 + ermg) * 288 + elr * 9 + eu];

                const size_t xb = ((size_t)(erow * TLEN + t)) * N3 + 2 * UNITS + ecol;
                float hh = tanhf(g_xproj[xb] + mp);
                float z  = zs[tid];
                float hv = hloc[tid];
                float hn = z * hv + (1.f - z) * hh;
                hloc[tid] = hn;
                g_hx[erow * UNITS + ecol] = f2tf32(hn);
                out[((size_t)(erow * TLEN + t)) * UNITS + ecol] = hn;
                if (t == TLEN - 1)
                    out[(size_t)BATCH * TLEN * UNITS + (size_t)erow * UNITS + ecol] = hn;
            }
        }
        grid_barrier();
    }
}

// ---------------------------------------------------------------------------
extern "C" void kernel_launch(void* const* d_in, const int* in_sizes, int n_in,
                              void* d_out, int out_size)
{
    const int*   x      = (const int*)d_in[0];
    const float* hidden = (const float*)d_in[1];
    const float* emb    = (const float*)d_in[2];
    const float* kern   = (const float*)d_in[3];
    const float* rk     = (const float*)d_in[4];
    const float* bias   = (const float*)d_in[5];
    float* out = (float*)d_out;

    static bool attr_set = false;
    if (!attr_set) {
        cudaFuncSetAttribute(gru_scan, cudaFuncAttributeMaxDynamicSharedMemorySize,
                             SMEM_FLOATS * sizeof(float));
        attr_set = true;
    }

    // Node 1: projection GEMM (tf32 tensor cores, fused embedding gather)
    xproj_tf32<<<dim3(N3 / 128, (BATCH * TLEN) / 128), 256>>>(x, emb, kern, bias);

    // Node 2: persistent GRU scan (tf32 tensor cores, cp.async broadcast)
    gru_scan<<<GRID, TPB, SMEM_FLOATS * sizeof(float)>>>(hidden, rk, out);
}